// round 4
// baseline (speedup 1.0000x reference)
#include <cuda_runtime.h>
#include <cuda_bf16.h>
#include <math.h>

#define IN_CH 128
#define H 4
#define C 16
#define HC 64
#define MAXN 100000
#define MAXE 1600000
#define NEG_SLOPE 0.2f
#define SCAN_BLK 256

// scratch (device globals — allocation is forbidden)
__device__ __align__(16) float g_xp[MAXN * HC];      // 25.6 MB
__device__ __align__(16) float g_asrc[MAXN * H];
__device__ __align__(16) float g_adst[MAXN * H];
__device__ __align__(16) float g_denom[MAXN * H];
__device__ __align__(16) float g_ev[MAXE * H];       // 25.6 MB, dst-sorted order
__device__ int  g_cnt[MAXN];
__device__ int  g_rowptr[MAXN + 1];
__device__ int  g_woff[MAXN];
__device__ int  g_bsum[512];
__device__ int  g_boff[512];
__device__ int2 g_sedge[MAXE];                       // (src, orig edge id), dst-sorted

// ---------------------------------------------------------------------------
// K-hist: histogram of dst into g_cnt  +  edge_index -> float copy
// ---------------------------------------------------------------------------
__global__ void k_hist(const int* __restrict__ ei, float* __restrict__ out_ei,
                       int e) {
    int twoE = 2 * e;
    for (int i = blockIdx.x * blockDim.x + threadIdx.x; i < twoE;
         i += gridDim.x * blockDim.x) {
        int v = ei[i];
        if (out_ei) out_ei[i] = (float)v;
        if (i >= e) atomicAdd(&g_cnt[v], 1);
    }
}

// ---------------------------------------------------------------------------
// scan: 3-phase exclusive prefix sum of g_cnt -> g_rowptr, copy to g_woff
// ---------------------------------------------------------------------------
__global__ void k_scan1(int n) {
    __shared__ int s[SCAN_BLK];
    int t = threadIdx.x;
    int i = blockIdx.x * SCAN_BLK + t;
    int v = (i < n) ? g_cnt[i] : 0;
    s[t] = v;
    __syncthreads();
    #pragma unroll
    for (int off = 1; off < SCAN_BLK; off <<= 1) {
        int a = (t >= off) ? s[t - off] : 0;
        __syncthreads();
        s[t] += a;
        __syncthreads();
    }
    if (i < n) g_rowptr[i] = s[t] - v;      // exclusive within block
    if (t == SCAN_BLK - 1) g_bsum[blockIdx.x] = s[t];
}

__global__ void k_scan2(int nb) {
    __shared__ int s[512];
    int t = threadIdx.x;
    int v = (t < nb) ? g_bsum[t] : 0;
    s[t] = v;
    __syncthreads();
    #pragma unroll
    for (int off = 1; off < 512; off <<= 1) {
        int a = (t >= off) ? s[t - off] : 0;
        __syncthreads();
        s[t] += a;
        __syncthreads();
    }
    g_boff[t] = s[t] - v;                   // exclusive
}

__global__ void k_scan3(int n, int e) {
    int i = blockIdx.x * blockDim.x + threadIdx.x;
    if (i == 0) g_rowptr[n] = e;
    if (i >= n) return;
    int r = g_rowptr[i] + g_boff[i >> 8];   // SCAN_BLK == 256
    g_rowptr[i] = r;
    g_woff[i] = r;
}

// ---------------------------------------------------------------------------
// K-permute: scatter edges into dst-sorted order
// ---------------------------------------------------------------------------
__global__ void k_permute(const int* __restrict__ ei, int e) {
    int i = blockIdx.x * blockDim.x + threadIdx.x;
    if (i >= e) return;
    int src = ei[i];
    int dst = ei[e + i];
    int r = atomicAdd(&g_woff[dst], 1);
    g_sedge[r] = make_int2(src, i);
}

// ---------------------------------------------------------------------------
// K1: xp = x @ W, fused a_src/a_dst. 64 nodes/block, 4x4 micro-tile / thread
// ---------------------------------------------------------------------------
__global__ __launch_bounds__(256) void k_gemm(
        const float* __restrict__ x, const float* __restrict__ W,
        const float* __restrict__ att_src, const float* __restrict__ att_dst,
        int n) {
    __shared__ float4 sW4[IN_CH * 16];
    __shared__ float  sx[64 * 129];
    int tid = threadIdx.x;
    int tx = tid & 15;
    int ty = tid >> 4;
    int node0 = blockIdx.x * 64;

    const float4* W4 = (const float4*)W;
    #pragma unroll
    for (int i = 0; i < (IN_CH * 16) / 256; i++)
        sW4[tid + i * 256] = W4[tid + i * 256];

    #pragma unroll
    for (int i = 0; i < (64 * IN_CH) / 256; i++) {
        int idx = tid + i * 256;
        int nn = idx >> 7, k = idx & 127;
        int node = node0 + nn;
        sx[nn * 129 + k] = (node < n) ? x[(size_t)node * IN_CH + k] : 0.f;
    }
    __syncthreads();

    float4 acc[4];
    #pragma unroll
    for (int j = 0; j < 4; j++) acc[j] = make_float4(0.f, 0.f, 0.f, 0.f);

    #pragma unroll 4
    for (int k = 0; k < IN_CH; k++) {
        float4 w = sW4[k * 16 + tx];
        #pragma unroll
        for (int j = 0; j < 4; j++) {
            float xv = sx[(ty * 4 + j) * 129 + k];
            acc[j].x = fmaf(xv, w.x, acc[j].x);
            acc[j].y = fmaf(xv, w.y, acc[j].y);
            acc[j].z = fmaf(xv, w.z, acc[j].z);
            acc[j].w = fmaf(xv, w.w, acc[j].w);
        }
    }

    float4 a_s = ((const float4*)att_src)[tx];
    float4 a_d = ((const float4*)att_dst)[tx];
    #pragma unroll
    for (int j = 0; j < 4; j++) {
        int node = node0 + ty * 4 + j;
        if (node < n)
            ((float4*)g_xp)[(size_t)node * 16 + tx] = acc[j];
        float s = acc[j].x * a_s.x + acc[j].y * a_s.y +
                  acc[j].z * a_s.z + acc[j].w * a_s.w;
        float d = acc[j].x * a_d.x + acc[j].y * a_d.y +
                  acc[j].z * a_d.z + acc[j].w * a_d.w;
        s += __shfl_xor_sync(0xffffffffu, s, 1, 4);
        s += __shfl_xor_sync(0xffffffffu, s, 2, 4);
        d += __shfl_xor_sync(0xffffffffu, d, 1, 4);
        d += __shfl_xor_sync(0xffffffffu, d, 2, 4);
        if ((tx & 3) == 0 && node < n) {
            g_asrc[node * H + (tx >> 2)] = s;
            g_adst[node * H + (tx >> 2)] = d;
        }
    }
}

// ---------------------------------------------------------------------------
// K-denom: warp per dst node. ev = exp(leaky(a_src[src]+a_dst[dst])),
// write ev (sorted), warp-reduce denom -> plain store (no atomics)
// ---------------------------------------------------------------------------
__global__ __launch_bounds__(256) void k_denom(int n) {
    int warp = (blockIdx.x * blockDim.x + threadIdx.x) >> 5;
    int lane = threadIdx.x & 31;
    if (warp >= n) return;
    int node = warp;
    int start = g_rowptr[node], end = g_rowptr[node + 1];
    float4 ad = ((const float4*)g_adst)[node];
    float4 sum = make_float4(0.f, 0.f, 0.f, 0.f);
    for (int pos = start + lane; pos < end; pos += 32) {
        int src = g_sedge[pos].x;
        float4 as = ((const float4*)g_asrc)[src];
        float4 l;
        l.x = as.x + ad.x; l.x = l.x > 0.f ? l.x : NEG_SLOPE * l.x;
        l.y = as.y + ad.y; l.y = l.y > 0.f ? l.y : NEG_SLOPE * l.y;
        l.z = as.z + ad.z; l.z = l.z > 0.f ? l.z : NEG_SLOPE * l.z;
        l.w = as.w + ad.w; l.w = l.w > 0.f ? l.w : NEG_SLOPE * l.w;
        float4 ev;
        ev.x = __expf(l.x); ev.y = __expf(l.y);
        ev.z = __expf(l.z); ev.w = __expf(l.w);
        ((float4*)g_ev)[pos] = ev;
        sum.x += ev.x; sum.y += ev.y; sum.z += ev.z; sum.w += ev.w;
    }
    #pragma unroll
    for (int off = 16; off >= 1; off >>= 1) {
        sum.x += __shfl_xor_sync(0xffffffffu, sum.x, off);
        sum.y += __shfl_xor_sync(0xffffffffu, sum.y, off);
        sum.z += __shfl_xor_sync(0xffffffffu, sum.z, off);
        sum.w += __shfl_xor_sync(0xffffffffu, sum.w, off);
    }
    if (lane == 0) ((float4*)g_denom)[node] = sum;
}

// ---------------------------------------------------------------------------
// K-agg: warp per dst node, lane owns 2 cols. Register accumulation,
// single coalesced store out = acc + bias. Writes alpha. No atomics.
// ---------------------------------------------------------------------------
__global__ __launch_bounds__(256) void k_agg(
        const float* __restrict__ bias, float* __restrict__ out,
        float* __restrict__ out_alpha, int n) {
    int warp = (blockIdx.x * blockDim.x + threadIdx.x) >> 5;
    int lane = threadIdx.x & 31;
    if (warp >= n) return;
    int node = warp;
    int start = g_rowptr[node], end = g_rowptr[node + 1];
    float4 den = ((const float4*)g_denom)[node];
    float4 inv;
    inv.x = 1.f / (den.x + 1e-16f);
    inv.y = 1.f / (den.y + 1e-16f);
    inv.z = 1.f / (den.z + 1e-16f);
    inv.w = 1.f / (den.w + 1e-16f);
    int h = lane >> 3;                      // head for my 2 cols
    float myinv = (h == 0) ? inv.x : (h == 1) ? inv.y : (h == 2) ? inv.z : inv.w;
    float linv  = (lane == 0) ? inv.x : (lane == 1) ? inv.y :
                  (lane == 2) ? inv.z : inv.w;   // used by lanes 0..3 for alpha
    float2 acc = make_float2(0.f, 0.f);

    for (int base = start; base < end; base += 32) {
        int m = end - base; if (m > 32) m = 32;
        int2 myse = (lane < m) ? g_sedge[base + lane] : make_int2(0, 0);
        for (int j = 0; j < m; j++) {
            int src = __shfl_sync(0xffffffffu, myse.x, j);
            int eid = __shfl_sync(0xffffffffu, myse.y, j);   // full-mask broadcast
            float ev = g_ev[(size_t)(base + j) * H + h];
            float alpha = ev * myinv;
            float2 v = *(const float2*)&g_xp[(size_t)src * HC + 2 * lane];
            acc.x = fmaf(v.x, alpha, acc.x);
            acc.y = fmaf(v.y, alpha, acc.y);
            if (lane < 4 && out_alpha) {
                float evl = g_ev[(size_t)(base + j) * H + lane];
                out_alpha[(size_t)eid * H + lane] = evl * linv;
            }
        }
    }
    float2 b = *(const float2*)&bias[2 * lane];
    float2 o;
    o.x = acc.x + b.x;
    o.y = acc.y + b.y;
    *(float2*)&out[(size_t)node * HC + 2 * lane] = o;
}

extern "C" void kernel_launch(void* const* d_in, const int* in_sizes, int n_in,
                              void* d_out, int out_size) {
    const float* x       = (const float*)d_in[0];
    const float* W       = (const float*)d_in[1];
    const float* att_src = (const float*)d_in[2];
    const float* att_dst = (const float*)d_in[3];
    const float* bias    = (const float*)d_in[4];
    const int*   ei      = (const int*)d_in[5];

    int n = in_sizes[0] / IN_CH;
    int e = in_sizes[5] / 2;

    float* out = (float*)d_out;
    float* out_ei = nullptr;
    float* out_alpha = nullptr;
    if (out_size >= n * HC + 2 * e) out_ei = out + (size_t)n * HC;
    if (out_size >= n * HC + 2 * e + e * H)
        out_alpha = out + (size_t)n * HC + 2 * e;

    // zero dst-degree counters
    void* cnt_ptr = nullptr;
    cudaGetSymbolAddress(&cnt_ptr, g_cnt);
    cudaMemsetAsync(cnt_ptr, 0, n * sizeof(int));

    // GEMM (independent of edge pipeline)
    k_gemm<<<(n + 63) / 64, 256>>>(x, W, att_src, att_dst, n);

    // histogram + edge_index float copy
    {
        int blocks = (2 * e + 255) / 256;
        if (blocks > 8192) blocks = 8192;
        k_hist<<<blocks, 256>>>(ei, out_ei, e);
    }

    // exclusive scan of counts -> rowptr, woff
    int nb = (n + SCAN_BLK - 1) / SCAN_BLK;
    k_scan1<<<nb, SCAN_BLK>>>(n);
    k_scan2<<<1, 512>>>(nb);
    k_scan3<<<(n + 255) / 256, 256>>>(n, e);

    // permute edges into dst-sorted order
    k_permute<<<(e + 255) / 256, 256>>>(ei, e);

    // per-node softmax denominator + ev
    k_denom<<<(n + 7) / 8, 256>>>(n);

    // per-node aggregation (atomic-free) + alpha + bias
    k_agg<<<(n + 7) / 8, 256>>>(bias, out, out_alpha, n);
}